// round 1
// baseline (speedup 1.0000x reference)
#include <cuda_runtime.h>
#include <math.h>

#define NUM_STEPS 30

// Inverse affines computed once per launch by a tiny kernel (no allocation).
__device__ float g_inv_affine[8 * 16];

__global__ void invert_affine_kernel(const float* __restrict__ affine, int B) {
    int b = threadIdx.x;
    if (b >= B) return;
    // Gauss-Jordan with partial pivoting, double precision, augmented [A | I].
    double m[4][8];
    #pragma unroll
    for (int i = 0; i < 4; i++) {
        #pragma unroll
        for (int j = 0; j < 4; j++) m[i][j] = (double)affine[b * 16 + i * 4 + j];
        #pragma unroll
        for (int j = 0; j < 4; j++) m[i][4 + j] = (i == j) ? 1.0 : 0.0;
    }
    for (int col = 0; col < 4; col++) {
        int piv = col;
        double best = fabs(m[col][col]);
        for (int r = col + 1; r < 4; r++) {
            double v = fabs(m[r][col]);
            if (v > best) { best = v; piv = r; }
        }
        if (piv != col) {
            for (int j = 0; j < 8; j++) { double t = m[col][j]; m[col][j] = m[piv][j]; m[piv][j] = t; }
        }
        double inv = 1.0 / m[col][col];
        for (int j = 0; j < 8; j++) m[col][j] *= inv;
        for (int r = 0; r < 4; r++) {
            if (r == col) continue;
            double f = m[r][col];
            for (int j = 0; j < 8; j++) m[r][j] -= f * m[col][j];
        }
    }
    #pragma unroll
    for (int i = 0; i < 4; i++)
        #pragma unroll
        for (int j = 0; j < 4; j++)
            g_inv_affine[b * 16 + i * 4 + j] = (float)m[i][4 + j];
}

__global__ __launch_bounds__(256)
void deform_kernel(const float* __restrict__ verts,
                   const float* __restrict__ affine,
                   const float* __restrict__ flow,
                   float* __restrict__ out,
                   int B, int N, int D, int H, int W)
{
    long long idx = (long long)blockIdx.x * blockDim.x + threadIdx.x;
    long long total = (long long)B * N;
    if (idx >= total) return;
    int b = (int)(idx / N);
    int n = (int)(idx % N);

    // ---- affine transform of homogeneous vertex ----
    const float* A = affine + b * 16;
    size_t vbase = ((size_t)b * N + n) * 3;
    float vx = verts[vbase + 0];
    float vy = verts[vbase + 1];
    float vz = verts[vbase + 2];

    float px = A[0] * vx + A[1] * vy + A[2]  * vz + A[3];
    float py = A[4] * vx + A[5] * vy + A[6]  * vz + A[7];
    float pz = A[8] * vx + A[9] * vy + A[10] * vz + A[11];

    // ---- Euler integration with per-thread corner cache ----
    const size_t HW  = (size_t)H * W;
    const size_t DHW = (size_t)D * HW;
    const float* base = flow + (size_t)b * 3 * DHW;
    const float scale = 1.0f / (float)NUM_STEPS;
    const float dmax = (float)(D - 1), hmax = (float)(H - 1), wmax = (float)(W - 1);

    float xd = px, xh = py, xw = pz;
    int cd = -1000000, ch = -1000000, cw = -1000000;
    float c[3][8];  // cached corner values: [channel][corner], corner bits = (d,h,w)

    #pragma unroll 1
    for (int s = 0; s < NUM_STEPS; s++) {
        float pdc = fminf(fmaxf(xd, 0.0f), dmax);
        float phc = fminf(fmaxf(xh, 0.0f), hmax);
        float pwc = fminf(fmaxf(xw, 0.0f), wmax);
        float fd0 = floorf(pdc), fh0 = floorf(phc), fw0 = floorf(pwc);
        int d0 = (int)fd0, h0 = (int)fh0, w0 = (int)fw0;
        float fd = pdc - fd0, fh = phc - fh0, fw = pwc - fw0;

        if (d0 != cd || h0 != ch || w0 != cw) {
            cd = d0; ch = h0; cw = w0;
            int d1 = min(d0 + 1, D - 1);
            int h1 = min(h0 + 1, H - 1);
            int w1 = min(w0 + 1, W - 1);
            size_t rd0 = (size_t)d0 * HW, rd1 = (size_t)d1 * HW;
            size_t rh0 = (size_t)h0 * W,  rh1 = (size_t)h1 * W;
            size_t o000 = rd0 + rh0 + (size_t)w0;
            size_t o001 = rd0 + rh0 + (size_t)w1;
            size_t o010 = rd0 + rh1 + (size_t)w0;
            size_t o011 = rd0 + rh1 + (size_t)w1;
            size_t o100 = rd1 + rh0 + (size_t)w0;
            size_t o101 = rd1 + rh0 + (size_t)w1;
            size_t o110 = rd1 + rh1 + (size_t)w0;
            size_t o111 = rd1 + rh1 + (size_t)w1;
            #pragma unroll
            for (int cc = 0; cc < 3; cc++) {
                const float* p = base + (size_t)cc * DHW;
                c[cc][0] = __ldg(p + o000);
                c[cc][1] = __ldg(p + o001);
                c[cc][2] = __ldg(p + o010);
                c[cc][3] = __ldg(p + o011);
                c[cc][4] = __ldg(p + o100);
                c[cc][5] = __ldg(p + o101);
                c[cc][6] = __ldg(p + o110);
                c[cc][7] = __ldg(p + o111);
            }
        }

        float omfw = 1.0f - fw;
        float omfh = 1.0f - fh;
        float omfd = 1.0f - fd;
        float samp[3];
        #pragma unroll
        for (int cc = 0; cc < 3; cc++) {
            // match reference lerp form: a*(1-f) + b*f
            float c00 = c[cc][0] * omfw + c[cc][1] * fw;
            float c01 = c[cc][2] * omfw + c[cc][3] * fw;
            float c10 = c[cc][4] * omfw + c[cc][5] * fw;
            float c11 = c[cc][6] * omfw + c[cc][7] * fw;
            float c0  = c00 * omfh + c01 * fh;
            float c1  = c10 * omfh + c11 * fh;
            samp[cc]  = c0 * omfd + c1 * fd;
        }
        xd += samp[0] * scale;
        xh += samp[1] * scale;
        xw += samp[2] * scale;
    }

    // ---- outputs ----
    float fix = xd - px;
    float fiy = xh - py;
    float fiz = xw - pz;

    const float* Inv = g_inv_affine + b * 16;
    float ox = Inv[0] * xd + Inv[1] * xh + Inv[2]  * xw + Inv[3];
    float oy = Inv[4] * xd + Inv[5] * xh + Inv[6]  * xw + Inv[7];
    float oz = Inv[8] * xd + Inv[9] * xh + Inv[10] * xw + Inv[11];

    // output 0: pred [B, N, 3]
    size_t pb = ((size_t)b * N + n) * 3;
    out[pb + 0] = ox;
    out[pb + 1] = oy;
    out[pb + 2] = oz;

    // output 1: flow_int [B, 3, N, 1, 1], after pred block
    size_t fb = (size_t)B * N * 3 + ((size_t)b * 3) * (size_t)N + n;
    out[fb + 0 * (size_t)N] = fix;
    out[fb + 1 * (size_t)N] = fiy;
    out[fb + 2 * (size_t)N] = fiz;
}

extern "C" void kernel_launch(void* const* d_in, const int* in_sizes, int n_in,
                              void* d_out, int out_size) {
    const float* verts  = (const float*)d_in[0];
    const float* affine = (const float*)d_in[1];
    const float* flow   = (const float*)d_in[2];
    float* out = (float*)d_out;

    int B = in_sizes[1] / 16;
    int N = in_sizes[0] / (3 * B);
    long long dhw = (long long)in_sizes[2] / (3LL * B);
    int D = (int)llrint(cbrt((double)dhw));
    int H = D, W = D;

    invert_affine_kernel<<<1, 32>>>(affine, B);

    long long total = (long long)B * N;
    int threads = 256;
    int blocks = (int)((total + threads - 1) / threads);
    deform_kernel<<<blocks, threads>>>(verts, affine, flow, out, B, N, D, H, W);
}